// round 1
// baseline (speedup 1.0000x reference)
#include <cuda_runtime.h>
#include <cuda_bf16.h>
#include <math.h>

// Problem constants (fixed shapes)
#define NTOK   8192        // B*S = 4*2048
#define DMODEL 1024
#define NEXP   32
#define ESIZE  256
#define TOPK   4

// ---------------- scratch (device globals; no runtime allocation) ----------------
__device__ int   g_counts[NEXP];
__device__ int   g_toklist[NEXP][NTOK];            // packed token*4 + slot
__device__ float g_gate[NTOK * TOPK];              // gate per (token, slot)
__device__ float g_H[(size_t)NTOK * TOPK * ESIZE]; // 32 MB: relu(x@K)*gate rows
__device__ float g_Ypart[(size_t)NTOK * TOPK * DMODEL]; // 128 MB: per-slot partial y

// ---------------- kernel 0: zero counts ----------------
__global__ void zero_counts_kernel() {
    if (threadIdx.x < NEXP) g_counts[threadIdx.x] = 0;
}

// ---------------- kernel 1: routing (1 warp per token) ----------------
__global__ __launch_bounds__(256) void route_kernel(const float* __restrict__ x,
                                                    const float* __restrict__ esel) {
    int gw   = (blockIdx.x * blockDim.x + threadIdx.x) >> 5;
    int lane = threadIdx.x & 31;
    if (gw >= NTOK) return;

    const float* xr = x + (size_t)gw * DMODEL;
    // keep the token's x row in registers: lane owns d = lane*4 + 128*j
    float4 xreg[8];
#pragma unroll
    for (int j = 0; j < 8; j++) xreg[j] = *(const float4*)(xr + lane * 4 + j * 128);

    float myv = -INFINITY;  // logit for expert == lane
#pragma unroll 1
    for (int e = 0; e < NEXP; e++) {
        const float* w = esel + (size_t)e * DMODEL;
        float acc = 0.f;
#pragma unroll
        for (int j = 0; j < 8; j++) {
            float4 wv = *(const float4*)(w + lane * 4 + j * 128);
            acc += xreg[j].x * wv.x + xreg[j].y * wv.y + xreg[j].z * wv.z + xreg[j].w * wv.w;
        }
#pragma unroll
        for (int off = 16; off; off >>= 1) acc += __shfl_xor_sync(0xffffffffu, acc, off);
        if (lane == e) myv = acc;
    }

    // top-4 with lowest-index tie-break (matches jax top_k ordering semantics)
    float v = myv;
#pragma unroll
    for (int k = 0; k < TOPK; k++) {
        float bv = v; int bi = lane;
#pragma unroll
        for (int off = 16; off; off >>= 1) {
            float ov = __shfl_xor_sync(0xffffffffu, bv, off);
            int   oi = __shfl_xor_sync(0xffffffffu, bi, off);
            if (ov > bv || (ov == bv && oi < bi)) { bv = ov; bi = oi; }
        }
        if (lane == 0) {
            float g = 1.f / (1.f + expf(-bv));          // sigmoid score = gate
            g_gate[gw * TOPK + k] = g;
            int pos = atomicAdd(&g_counts[bi], 1);
            g_toklist[bi][pos] = gw * TOPK + k;          // packed (token, slot)
        }
        if (lane == bi) v = -INFINITY;
    }
}

// ---------------- fused per-expert GEMM (128x128 tile, BK=16, 8x8 thread tile) ----
// IS_G1: A = x gathered by token (K=1024), B = keys[e] (ldb=256),
//        C = g_H[packed*256], epilogue relu * gate
// else : A = g_H gathered by packed row (K=256), B = values[e] (ldb=1024),
//        C = g_Ypart[packed*1024], plain store
template <int KDIM, int LDB, bool IS_G1>
__global__ __launch_bounds__(256, 2) void moe_gemm_kernel(const float* __restrict__ x,
                                                          const float* __restrict__ Ball) {
    const int e   = blockIdx.z;
    const int cnt = g_counts[e];
    const int m0  = blockIdx.y * 128;
    if (m0 >= cnt) return;
    const int n0  = blockIdx.x * 128;

    __shared__ float As[16][132];
    __shared__ float Bs[16][128];
    __shared__ int   sPacked[128];
    __shared__ float sGate[128];

    const int tid = threadIdx.x;

    if (tid < 128) {
        int m = m0 + tid;
        int packed = (m < cnt) ? g_toklist[e][m] : -1;
        sPacked[tid] = packed;
        sGate[tid]   = (IS_G1 && packed >= 0) ? g_gate[packed] : 0.f;
    }
    __syncthreads();

    const int ty = tid >> 4;          // 0..15
    const int tx = tid & 15;          // 0..15

    // A gather assignment: each thread loads row (tid>>1), float4 quads {aq0, aq0+1}
    const int arow = tid >> 1;
    const int aq0  = (tid & 1) * 2;
    const int apk  = sPacked[arow];
    const float* Aptr = nullptr;
    if (apk >= 0) {
        Aptr = IS_G1 ? (x + (size_t)(apk >> 2) * DMODEL)
                     : (g_H + (size_t)apk * ESIZE);
    }
    const float* Bp = Ball + (size_t)e * KDIM * LDB + n0;

    float c[8][8];
#pragma unroll
    for (int i = 0; i < 8; i++)
#pragma unroll
        for (int j = 0; j < 8; j++) c[i][j] = 0.f;

    for (int k0 = 0; k0 < KDIM; k0 += 16) {
        // A tile -> As[k][m] (transposed store)
#pragma unroll
        for (int j = 0; j < 2; j++) {
            int q = aq0 + j;
            float4 v = make_float4(0.f, 0.f, 0.f, 0.f);
            if (Aptr) v = *(const float4*)(Aptr + k0 + q * 4);
            As[q * 4 + 0][arow] = v.x;
            As[q * 4 + 1][arow] = v.y;
            As[q * 4 + 2][arow] = v.z;
            As[q * 4 + 3][arow] = v.w;
        }
        // B tile -> Bs[k][n]
#pragma unroll
        for (int p = 0; p < 2; p++) {
            int lin = tid + p * 256;
            int kk = lin >> 5, nq = lin & 31;
            float4 v = *(const float4*)(Bp + (size_t)(k0 + kk) * LDB + nq * 4);
            *(float4*)&Bs[kk][nq * 4] = v;
        }
        __syncthreads();

#pragma unroll
        for (int kk = 0; kk < 16; kk++) {
            float4 a0 = *(const float4*)&As[kk][ty * 8];
            float4 a1 = *(const float4*)&As[kk][ty * 8 + 4];
            float4 b0 = *(const float4*)&Bs[kk][tx * 8];
            float4 b1 = *(const float4*)&Bs[kk][tx * 8 + 4];
            float av[8] = {a0.x, a0.y, a0.z, a0.w, a1.x, a1.y, a1.z, a1.w};
            float bv[8] = {b0.x, b0.y, b0.z, b0.w, b1.x, b1.y, b1.z, b1.w};
#pragma unroll
            for (int i = 0; i < 8; i++)
#pragma unroll
                for (int j = 0; j < 8; j++) c[i][j] = fmaf(av[i], bv[j], c[i][j]);
        }
        __syncthreads();
    }

    // epilogue
#pragma unroll
    for (int i = 0; i < 8; i++) {
        int m = ty * 8 + i;
        int packed = sPacked[m];
        if (packed < 0) continue;
        float scale = sGate[m];
        float* out = IS_G1 ? (g_H + (size_t)packed * ESIZE + n0)
                           : (g_Ypart + (size_t)packed * DMODEL + n0);
#pragma unroll
        for (int j = 0; j < 8; j += 4) {
            float4 v;
            if (IS_G1) {
                v.x = fmaxf(c[i][j + 0], 0.f) * scale;
                v.y = fmaxf(c[i][j + 1], 0.f) * scale;
                v.z = fmaxf(c[i][j + 2], 0.f) * scale;
                v.w = fmaxf(c[i][j + 3], 0.f) * scale;
            } else {
                v.x = c[i][j + 0]; v.y = c[i][j + 1];
                v.z = c[i][j + 2]; v.w = c[i][j + 3];
            }
            *(float4*)(out + tx * 8 + j) = v;
        }
    }
}

// ---------------- kernel 4: reduce 4 partial rows per token into y ----------------
__global__ __launch_bounds__(256) void reduce_kernel(float* __restrict__ y) {
    int idx = blockIdx.x * blockDim.x + threadIdx.x;  // over NTOK*256 float4s
    if (idx >= NTOK * (DMODEL / 4)) return;
    int t  = idx >> 8;          // DMODEL/4 = 256 float4 per row
    int d4 = idx & 255;
    const float4* P = (const float4*)g_Ypart;
    size_t base = (size_t)t * TOPK * (DMODEL / 4) + d4;
    float4 a = P[base + 0 * (DMODEL / 4)];
    float4 b = P[base + 1 * (DMODEL / 4)];
    float4 cc = P[base + 2 * (DMODEL / 4)];
    float4 d = P[base + 3 * (DMODEL / 4)];
    float4 r;
    r.x = a.x + b.x + cc.x + d.x;
    r.y = a.y + b.y + cc.y + d.y;
    r.z = a.z + b.z + cc.z + d.z;
    r.w = a.w + b.w + cc.w + d.w;
    ((float4*)y)[idx] = r;
}

// ---------------- launch ----------------
extern "C" void kernel_launch(void* const* d_in, const int* in_sizes, int n_in,
                              void* d_out, int out_size) {
    const float* x      = (const float*)d_in[0];
    const float* keys   = (const float*)d_in[1];
    const float* values = (const float*)d_in[2];
    const float* esel   = (const float*)d_in[3];
    float*       y      = (float*)d_out;

    zero_counts_kernel<<<1, 32>>>();
    route_kernel<<<(NTOK * 32) / 256, 256>>>(x, esel);

    dim3 g1(ESIZE / 128, NTOK / 128, NEXP);   // (2, 64, 32)
    moe_gemm_kernel<DMODEL, ESIZE, true><<<g1, 256>>>(x, keys);

    dim3 g2(DMODEL / 128, NTOK / 128, NEXP);  // (8, 64, 32)
    moe_gemm_kernel<ESIZE, DMODEL, false><<<g2, 256>>>(x, values);

    reduce_kernel<<<(NTOK * (DMODEL / 4)) / 256, 256>>>(y);
}

// round 3
// speedup vs baseline: 2.9038x; 2.9038x over previous
#include <cuda_runtime.h>
#include <cuda_fp16.h>
#include <math.h>
#include <stdint.h>

// Problem constants (fixed shapes)
#define NTOK   8192        // B*S
#define DMODEL 1024
#define NEXP   32
#define ESIZE  256
#define TOPK   4

// ---------------- scratch (device globals) ----------------
__device__ int    g_counts[NEXP];
__device__ int    g_toklist[NEXP][NTOK];             // packed token*4 + slot
__device__ float  g_gate[NTOK * TOPK];
__device__ __half g_xh[(size_t)NTOK * DMODEL];                 // fp16 x
__device__ __half g_keysT[(size_t)NEXP * ESIZE * DMODEL];      // [e][h][d] fp16
__device__ __half g_valuesT[(size_t)NEXP * DMODEL * ESIZE];    // [e][v][h] fp16
__device__ __half g_Hh[(size_t)NTOK * TOPK * ESIZE];           // fp16 H rows
__device__ float  g_Ypart[(size_t)NTOK * TOPK * DMODEL];       // fp32 partials

__device__ __forceinline__ uint32_t smem_u32(const void* p) {
    uint32_t a;
    asm("{ .reg .u64 t; cvta.to.shared.u64 t, %1; cvt.u32.u64 %0, t; }" : "=r"(a) : "l"(p));
    return a;
}

// ---------------- kernel 0: zero counts ----------------
__global__ void zero_counts_kernel() {
    if (threadIdx.x < NEXP) g_counts[threadIdx.x] = 0;
}

// ---------------- kernel 1: routing (1 warp per token) ----------------
__global__ __launch_bounds__(256) void route_kernel(const float* __restrict__ x,
                                                    const float* __restrict__ esel) {
    int gw   = (blockIdx.x * blockDim.x + threadIdx.x) >> 5;
    int lane = threadIdx.x & 31;
    if (gw >= NTOK) return;

    const float* xr = x + (size_t)gw * DMODEL;
    float4 xreg[8];
#pragma unroll
    for (int j = 0; j < 8; j++) xreg[j] = *(const float4*)(xr + lane * 4 + j * 128);

    float myv = -INFINITY;
#pragma unroll 1
    for (int e = 0; e < NEXP; e++) {
        const float* w = esel + (size_t)e * DMODEL;
        float acc = 0.f;
#pragma unroll
        for (int j = 0; j < 8; j++) {
            float4 wv = *(const float4*)(w + lane * 4 + j * 128);
            acc += xreg[j].x * wv.x + xreg[j].y * wv.y + xreg[j].z * wv.z + xreg[j].w * wv.w;
        }
#pragma unroll
        for (int off = 16; off; off >>= 1) acc += __shfl_xor_sync(0xffffffffu, acc, off);
        if (lane == e) myv = acc;
    }

    float v = myv;
#pragma unroll
    for (int k = 0; k < TOPK; k++) {
        float bv = v; int bi = lane;
#pragma unroll
        for (int off = 16; off; off >>= 1) {
            float ov = __shfl_xor_sync(0xffffffffu, bv, off);
            int   oi = __shfl_xor_sync(0xffffffffu, bi, off);
            if (ov > bv || (ov == bv && oi < bi)) { bv = ov; bi = oi; }
        }
        if (lane == 0) {
            float g = 1.f / (1.f + expf(-bv));
            g_gate[gw * TOPK + k] = g;
            int pos = atomicAdd(&g_counts[bi], 1);
            g_toklist[bi][pos] = gw * TOPK + k;
        }
        if (lane == bi) v = -INFINITY;
    }
}

// ---------------- kernel 2: x -> fp16 ----------------
__global__ __launch_bounds__(256) void convert_x_kernel(const float* __restrict__ x) {
    int idx = blockIdx.x * blockDim.x + threadIdx.x;
    if (idx >= NTOK * DMODEL / 8) return;
    const float4* in = (const float4*)x;
    float4 a = in[idx * 2], b = in[idx * 2 + 1];
    __half2 h0 = __floats2half2_rn(a.x, a.y);
    __half2 h1 = __floats2half2_rn(a.z, a.w);
    __half2 h2 = __floats2half2_rn(b.x, b.y);
    __half2 h3 = __floats2half2_rn(b.z, b.w);
    uint4 o;
    o.x = *(uint32_t*)&h0; o.y = *(uint32_t*)&h1; o.z = *(uint32_t*)&h2; o.w = *(uint32_t*)&h3;
    ((uint4*)g_xh)[idx] = o;
}

// ---------------- kernel 3: transpose+convert: in[e][r][c] f32 -> out[e][c][r] f16 ----
__global__ __launch_bounds__(256) void transpose_f2h_kernel(const float* __restrict__ in,
                                                            __half* __restrict__ out,
                                                            int R, int C) {
    __shared__ float t[32][33];
    int e = blockIdx.z;
    int r0 = blockIdx.y * 32, c0 = blockIdx.x * 32;
    const float* src = in + (size_t)e * R * C;
    __half* dst = out + (size_t)e * R * C;
    int tx = threadIdx.x & 31, ty = threadIdx.x >> 5;
#pragma unroll
    for (int i = 0; i < 32; i += 8) t[ty + i][tx] = src[(size_t)(r0 + ty + i) * C + c0 + tx];
    __syncthreads();
#pragma unroll
    for (int i = 0; i < 32; i += 8)
        dst[(size_t)(c0 + ty + i) * R + r0 + tx] = __float2half(t[tx][ty + i]);
}

// ---------------- HMMA fp16 GEMM (BM=128, BN=128, BK=32, 8 warps 2m x 4n) --------
// IS_G1: A = g_xh gathered by token (K=1024), B = g_keysT[e]; epi relu*gate -> g_Hh
// else : A = g_Hh gathered by packed (K=256), B = g_valuesT[e]; epi plain -> g_Ypart
#define ASTRIDE 40   // halves per smem row (80B) -> conflict-free ldmatrix

__device__ __forceinline__ void ldsm_x4(uint32_t (&r)[4], uint32_t addr) {
    asm volatile("ldmatrix.sync.aligned.m8n8.x4.shared.b16 {%0,%1,%2,%3}, [%4];"
                 : "=r"(r[0]), "=r"(r[1]), "=r"(r[2]), "=r"(r[3]) : "r"(addr));
}
__device__ __forceinline__ void mma16816(float (&c)[4], const uint32_t (&a)[4],
                                         uint32_t b0, uint32_t b1) {
    asm volatile(
        "mma.sync.aligned.m16n8k16.row.col.f32.f16.f16.f32 "
        "{%0,%1,%2,%3}, {%4,%5,%6,%7}, {%8,%9}, {%0,%1,%2,%3};"
        : "+f"(c[0]), "+f"(c[1]), "+f"(c[2]), "+f"(c[3])
        : "r"(a[0]), "r"(a[1]), "r"(a[2]), "r"(a[3]), "r"(b0), "r"(b1));
}

template <int KDIM, bool IS_G1>
__global__ __launch_bounds__(256) void moe_hmma_kernel() {
    __shared__ __align__(16) __half As[2][128 * ASTRIDE];
    __shared__ __align__(16) __half Bs[2][128 * ASTRIDE];
    __shared__ int   sPacked[128];
    __shared__ float sGate[128];

    const int e   = blockIdx.z;
    const int cnt = g_counts[e];
    const int m0  = blockIdx.y * 128;
    if (m0 >= cnt) return;
    const int n0  = blockIdx.x * 128;

    const int tid    = threadIdx.x;
    const int lane   = tid & 31;
    const int wid    = tid >> 5;
    const int warp_m = wid & 1;      // 0..1 -> 64 rows each
    const int warp_n = wid >> 1;     // 0..3 -> 32 cols each

    if (tid < 128) {
        int m = m0 + tid;
        int p = (m < cnt) ? g_toklist[e][m] : -1;
        sPacked[tid] = p;
        sGate[tid]   = (IS_G1 && p >= 0) ? g_gate[p] : 0.f;
    }
    __syncthreads();

    // per-thread global load assignment: row = tid>>1, two uint4 quads
    const int grow = tid >> 1;
    const int gq   = (tid & 1) * 2;
    const int apk  = sPacked[grow];
    const __half* Arow = (apk >= 0)
        ? (IS_G1 ? (g_xh + (size_t)(apk >> 2) * KDIM) : (g_Hh + (size_t)apk * KDIM))
        : nullptr;
    const __half* Bbase = IS_G1 ? (g_keysT   + (size_t)e * ESIZE * DMODEL)
                                : (g_valuesT + (size_t)e * DMODEL * ESIZE);
    const __half* Brow = Bbase + (size_t)(n0 + grow) * KDIM;

    float c[4][4][4];
#pragma unroll
    for (int i = 0; i < 4; i++)
#pragma unroll
        for (int j = 0; j < 4; j++)
#pragma unroll
            for (int k = 0; k < 4; k++) c[i][j][k] = 0.f;

    const uint32_t sA0 = smem_u32(&As[0][0]);
    const uint32_t sB0 = smem_u32(&Bs[0][0]);
    const int lr = lane & 15;
    const int lk = (lane >> 4) * 8;

    uint4 pa[2], pb[2];
    const int S = KDIM / 32;

    // prologue: tile 0
#pragma unroll
    for (int j = 0; j < 2; j++) {
        pa[j] = Arow ? *(const uint4*)(Arow + (gq + j) * 8) : make_uint4(0, 0, 0, 0);
        pb[j] = *(const uint4*)(Brow + (gq + j) * 8);
    }
#pragma unroll
    for (int j = 0; j < 2; j++) {
        *(uint4*)(&As[0][grow * ASTRIDE + (gq + j) * 8]) = pa[j];
        *(uint4*)(&Bs[0][grow * ASTRIDE + (gq + j) * 8]) = pb[j];
    }
    __syncthreads();

#pragma unroll 1
    for (int s = 0; s < S; s++) {
        if (s + 1 < S) {
            const int k0 = (s + 1) * 32;
#pragma unroll
            for (int j = 0; j < 2; j++) {
                pa[j] = Arow ? *(const uint4*)(Arow + k0 + (gq + j) * 8) : make_uint4(0, 0, 0, 0);
                pb[j] = *(const uint4*)(Brow + k0 + (gq + j) * 8);
            }
        }
        const int buf = s & 1;
        const uint32_t sA = sA0 + buf * (128 * ASTRIDE * 2);
        const uint32_t sB = sB0 + buf * (128 * ASTRIDE * 2);
#pragma unroll
        for (int kk = 0; kk < 32; kk += 16) {
            uint32_t a[4][4];
#pragma unroll
            for (int mt = 0; mt < 4; mt++) {
                uint32_t addr = sA + ((warp_m * 64 + mt * 16 + lr) * ASTRIDE + kk + lk) * 2;
                ldsm_x4(a[mt], addr);
            }
            uint32_t b[2][4];
#pragma unroll
            for (int p = 0; p < 2; p++) {
                uint32_t addr = sB + ((warp_n * 32 + p * 16 + lr) * ASTRIDE + kk + lk) * 2;
                ldsm_x4(b[p], addr);
            }
#pragma unroll
            for (int mt = 0; mt < 4; mt++)
#pragma unroll
                for (int nt = 0; nt < 4; nt++)
                    mma16816(c[mt][nt], a[mt], b[nt >> 1][nt & 1], b[nt >> 1][2 + (nt & 1)]);
        }
        if (s + 1 < S) {
            const int nbuf = (s + 1) & 1;
#pragma unroll
            for (int j = 0; j < 2; j++) {
                *(uint4*)(&As[nbuf][grow * ASTRIDE + (gq + j) * 8]) = pa[j];
                *(uint4*)(&Bs[nbuf][grow * ASTRIDE + (gq + j) * 8]) = pb[j];
            }
            __syncthreads();
        }
    }

    // epilogue: thread holds c[mt][nt]: rows mt*16 + lane/4 (+8), cols nt*8 + 2*(lane&3)
    const int erow = lane >> 2;
    const int ecol = (lane & 3) * 2;
#pragma unroll
    for (int mt = 0; mt < 4; mt++) {
#pragma unroll
        for (int h = 0; h < 2; h++) {
            int ml = warp_m * 64 + mt * 16 + erow + h * 8;
            int packed = sPacked[ml];
            if (packed < 0) continue;
            if (IS_G1) {
                float gate = sGate[ml];
                __half* dst = g_Hh + (size_t)packed * ESIZE + n0 + warp_n * 32 + ecol;
#pragma unroll
                for (int nt = 0; nt < 4; nt++) {
                    float f0 = fmaxf(c[mt][nt][2 * h + 0], 0.f) * gate;
                    float f1 = fmaxf(c[mt][nt][2 * h + 1], 0.f) * gate;
                    *(__half2*)(dst + nt * 8) = __floats2half2_rn(f0, f1);
                }
            } else {
                float* dst = g_Ypart + (size_t)packed * DMODEL + n0 + warp_n * 32 + ecol;
#pragma unroll
                for (int nt = 0; nt < 4; nt++) {
                    float2 v = make_float2(c[mt][nt][2 * h + 0], c[mt][nt][2 * h + 1]);
                    *(float2*)(dst + nt * 8) = v;
                }
            }
        }
    }
}

// ---------------- reduce 4 partial rows per token into y ----------------
__global__ __launch_bounds__(256) void reduce_kernel(float* __restrict__ y) {
    int idx = blockIdx.x * blockDim.x + threadIdx.x;
    if (idx >= NTOK * (DMODEL / 4)) return;
    int t  = idx >> 8;
    int d4 = idx & 255;
    const float4* P = (const float4*)g_Ypart;
    size_t base = (size_t)t * TOPK * (DMODEL / 4) + d4;
    float4 a = P[base + 0 * (DMODEL / 4)];
    float4 b = P[base + 1 * (DMODEL / 4)];
    float4 c = P[base + 2 * (DMODEL / 4)];
    float4 d = P[base + 3 * (DMODEL / 4)];
    float4 r;
    r.x = a.x + b.x + c.x + d.x;
    r.y = a.y + b.y + c.y + d.y;
    r.z = a.z + b.z + c.z + d.z;
    r.w = a.w + b.w + c.w + d.w;
    ((float4*)y)[idx] = r;
}

// ---------------- launch ----------------
extern "C" void kernel_launch(void* const* d_in, const int* in_sizes, int n_in,
                              void* d_out, int out_size) {
    const float* x      = (const float*)d_in[0];
    const float* keys   = (const float*)d_in[1];
    const float* values = (const float*)d_in[2];
    const float* esel   = (const float*)d_in[3];
    float*       y      = (float*)d_out;

    zero_counts_kernel<<<1, 32>>>();
    route_kernel<<<(NTOK * 32) / 256, 256>>>(x, esel);

    convert_x_kernel<<<(NTOK * DMODEL / 8 + 255) / 256, 256>>>(x);

    __half* keysT_p;   cudaGetSymbolAddress((void**)&keysT_p, g_keysT);
    __half* valuesT_p; cudaGetSymbolAddress((void**)&valuesT_p, g_valuesT);
    dim3 tk(ESIZE / 32, DMODEL / 32, NEXP);   // keys: R=1024, C=256
    transpose_f2h_kernel<<<tk, 256>>>(keys, keysT_p, DMODEL, ESIZE);
    dim3 tv(DMODEL / 32, ESIZE / 32, NEXP);   // values: R=256, C=1024
    transpose_f2h_kernel<<<tv, 256>>>(values, valuesT_p, ESIZE, DMODEL);

    dim3 g1(ESIZE / 128, NTOK / 128, NEXP);   // (2, 64, 32)
    moe_hmma_kernel<DMODEL, true><<<g1, 256>>>();

    dim3 g2(DMODEL / 128, NTOK / 128, NEXP);  // (8, 64, 32)
    moe_hmma_kernel<ESIZE, false><<<g2, 256>>>();

    reduce_kernel<<<(NTOK * (DMODEL / 4)) / 256, 256>>>(y);
}

// round 4
// speedup vs baseline: 3.3723x; 1.1613x over previous
#include <cuda_runtime.h>
#include <cuda_fp16.h>
#include <math.h>
#include <stdint.h>

// Problem constants (fixed shapes)
#define NTOK   8192        // B*S
#define DMODEL 1024
#define NEXP   32
#define ESIZE  256
#define TOPK   4

// ---------------- scratch (device globals) ----------------
__device__ int    g_counts[NEXP];
__device__ int    g_toklist[NEXP][NTOK];             // packed token*4 + slot
__device__ float  g_gate[NTOK * TOPK];
__device__ __half g_xh[(size_t)NTOK * DMODEL];                 // fp16 x (from route)
__device__ __half g_keysH[(size_t)NEXP * DMODEL * ESIZE];      // fp16 keys, orig layout [e][d][h]
__device__ __half g_valuesH[(size_t)NEXP * ESIZE * DMODEL];    // fp16 values, orig layout [e][h][v]
__device__ __half g_Hh[(size_t)NTOK * TOPK * ESIZE];           // fp16 H rows
__device__ __half g_Yph[(size_t)NTOK * TOPK * DMODEL];         // fp16 partial y

__device__ __forceinline__ uint32_t smem_u32(const void* p) {
    uint32_t a;
    asm("{ .reg .u64 t; cvta.to.shared.u64 t, %1; cvt.u32.u64 %0, t; }" : "=r"(a) : "l"(p));
    return a;
}
#define CP_ASYNC16(dst, src) \
    asm volatile("cp.async.cg.shared.global [%0], [%1], 16;" :: "r"(dst), "l"(src))
#define CP_COMMIT() asm volatile("cp.async.commit_group;" ::: "memory")
#define CP_WAIT2()  asm volatile("cp.async.wait_group 2;" ::: "memory")

// ---------------- kernel 0: zero counts ----------------
__global__ void zero_counts_kernel() {
    if (threadIdx.x < NEXP) g_counts[threadIdx.x] = 0;
}

// ---------------- kernel 1: routing + x->fp16 (1 warp per token) ----------------
__global__ __launch_bounds__(256) void route_kernel(const float* __restrict__ x,
                                                    const float* __restrict__ esel) {
    int gw   = (blockIdx.x * blockDim.x + threadIdx.x) >> 5;
    int lane = threadIdx.x & 31;
    if (gw >= NTOK) return;

    const float* xr = x + (size_t)gw * DMODEL;
    float4 xreg[8];
#pragma unroll
    for (int j = 0; j < 8; j++) xreg[j] = *(const float4*)(xr + lane * 4 + j * 128);

    // fused fp16 conversion of x
#pragma unroll
    for (int j = 0; j < 8; j++) {
        __half2 h0 = __floats2half2_rn(xreg[j].x, xreg[j].y);
        __half2 h1 = __floats2half2_rn(xreg[j].z, xreg[j].w);
        uint2 o; o.x = *(uint32_t*)&h0; o.y = *(uint32_t*)&h1;
        *(uint2*)(g_xh + (size_t)gw * DMODEL + lane * 4 + j * 128) = o;
    }

    float myv = -INFINITY;
#pragma unroll 1
    for (int e = 0; e < NEXP; e++) {
        const float* w = esel + (size_t)e * DMODEL;
        float acc = 0.f;
#pragma unroll
        for (int j = 0; j < 8; j++) {
            float4 wv = *(const float4*)(w + lane * 4 + j * 128);
            acc += xreg[j].x * wv.x + xreg[j].y * wv.y + xreg[j].z * wv.z + xreg[j].w * wv.w;
        }
#pragma unroll
        for (int off = 16; off; off >>= 1) acc += __shfl_xor_sync(0xffffffffu, acc, off);
        if (lane == e) myv = acc;
    }

    float v = myv;
#pragma unroll
    for (int k = 0; k < TOPK; k++) {
        float bv = v; int bi = lane;
#pragma unroll
        for (int off = 16; off; off >>= 1) {
            float ov = __shfl_xor_sync(0xffffffffu, bv, off);
            int   oi = __shfl_xor_sync(0xffffffffu, bi, off);
            if (ov > bv || (ov == bv && oi < bi)) { bv = ov; bi = oi; }
        }
        if (lane == 0) {
            float g = 1.f / (1.f + expf(-bv));
            g_gate[gw * TOPK + k] = g;
            int pos = atomicAdd(&g_counts[bi], 1);
            g_toklist[bi][pos] = gw * TOPK + k;
        }
        if (lane == bi) v = -INFINITY;
    }
}

// ---------------- kernel 2: elementwise f32 -> f16 (weights) ----------------
__global__ __launch_bounds__(256) void convert_h_kernel(const float* __restrict__ in,
                                                        __half* __restrict__ out, int n8) {
    int idx = blockIdx.x * blockDim.x + threadIdx.x;
    if (idx >= n8) return;
    const float4* p = (const float4*)in;
    float4 a = p[idx * 2], b = p[idx * 2 + 1];
    __half2 h0 = __floats2half2_rn(a.x, a.y);
    __half2 h1 = __floats2half2_rn(a.z, a.w);
    __half2 h2 = __floats2half2_rn(b.x, b.y);
    __half2 h3 = __floats2half2_rn(b.z, b.w);
    uint4 o;
    o.x = *(uint32_t*)&h0; o.y = *(uint32_t*)&h1; o.z = *(uint32_t*)&h2; o.w = *(uint32_t*)&h3;
    ((uint4*)out)[idx] = o;
}

// ---------------- HMMA fp16 GEMM: BM=128, BN=256, BK=32, 8 warps (2m x 4n, 64x64) --
// A [m][k] fp16 gathered rows; B [k][n] fp16 (original layout) via ldmatrix.trans.
// IS_G1: A = g_xh (K=1024), B = g_keysH[e]; epi relu*gate -> g_Hh
// else : A = g_Hh (K=256),  B = g_valuesH[e]; epi plain -> g_Yph
#define ASTRIDE 40    // halves per A smem row (80B): conflict-free non-trans ldmatrix
#define BSTRIDE 264   // halves per B smem row (528B): conflict-free trans ldmatrix
#define NSTAGE  4
#define A_ST_BYTES (128 * ASTRIDE * 2)   // 10240
#define B_ST_BYTES (32 * BSTRIDE * 2)    // 16896
#define SM_OFF_A   1024
#define SM_OFF_B   (SM_OFF_A + NSTAGE * A_ST_BYTES)
#define SM_TOTAL   (SM_OFF_B + NSTAGE * B_ST_BYTES)

__device__ __forceinline__ void ldsm_x4(uint32_t (&r)[4], uint32_t addr) {
    asm volatile("ldmatrix.sync.aligned.m8n8.x4.shared.b16 {%0,%1,%2,%3}, [%4];"
                 : "=r"(r[0]), "=r"(r[1]), "=r"(r[2]), "=r"(r[3]) : "r"(addr));
}
__device__ __forceinline__ void ldsm_x4_trans(uint32_t (&r)[4], uint32_t addr) {
    asm volatile("ldmatrix.sync.aligned.m8n8.x4.trans.shared.b16 {%0,%1,%2,%3}, [%4];"
                 : "=r"(r[0]), "=r"(r[1]), "=r"(r[2]), "=r"(r[3]) : "r"(addr));
}
__device__ __forceinline__ void mma16816(float (&c)[4], const uint32_t (&a)[4],
                                         uint32_t b0, uint32_t b1) {
    asm volatile(
        "mma.sync.aligned.m16n8k16.row.col.f32.f16.f16.f32 "
        "{%0,%1,%2,%3}, {%4,%5,%6,%7}, {%8,%9}, {%0,%1,%2,%3};"
        : "+f"(c[0]), "+f"(c[1]), "+f"(c[2]), "+f"(c[3])
        : "r"(a[0]), "r"(a[1]), "r"(a[2]), "r"(a[3]), "r"(b0), "r"(b1));
}

template <int KDIM, int N_LD, bool IS_G1>
__global__ __launch_bounds__(256) void moe_hmma_kernel() {
    extern __shared__ char smem[];
    const int e   = blockIdx.z;
    const int cnt = g_counts[e];
    const int m0  = blockIdx.y * 128;
    if (m0 >= cnt) return;
    const int n0  = blockIdx.x * 256;

    int*   sPacked = (int*)(smem);
    float* sGate   = (float*)(smem + 512);

    const int tid    = threadIdx.x;
    const int lane   = tid & 31;
    const int wid    = tid >> 5;
    const int warp_m = wid & 1;      // 0..1 -> 64 rows
    const int warp_n = wid >> 1;     // 0..3 -> 64 cols

    if (tid < 128) {
        int m = m0 + tid;
        int p = (m < cnt) ? g_toklist[e][m] : -1;
        sPacked[tid] = p;
        sGate[tid]   = (IS_G1 && p >= 0) ? g_gate[p] : 0.f;
    }
    __syncthreads();

    // global load assignment
    const int arow = tid >> 1;                 // A: row, 2 chunks of 16B
    const int ac0  = (tid & 1) * 2;
    const int apk  = sPacked[arow];
    const __half* Arow = (apk >= 0)
        ? (IS_G1 ? (g_xh + (size_t)(apk >> 2) * KDIM) : (g_Hh + (size_t)apk * KDIM))
        : (IS_G1 ? g_xh : g_Hh);               // dummy valid row; epilogue skips
    const __half* Bsrc = (IS_G1 ? g_keysH : g_valuesH) + (size_t)e * KDIM * N_LD + n0;

    const uint32_t sb = smem_u32(smem);

    // stage issue: A 2 chunks/thread, B 4 chunks/thread
    auto issue_stage = [&](int s) {
        const int st = s & (NSTAGE - 1);
        const int k0 = s * 32;
        uint32_t ad = sb + SM_OFF_A + st * A_ST_BYTES + arow * (ASTRIDE * 2);
#pragma unroll
        for (int j = 0; j < 2; j++)
            CP_ASYNC16(ad + (ac0 + j) * 16, Arow + k0 + (ac0 + j) * 8);
        uint32_t bd = sb + SM_OFF_B + st * B_ST_BYTES;
#pragma unroll
        for (int j = 0; j < 4; j++) {
            int idx = tid + 256 * j;
            int row = idx >> 5, c16 = idx & 31;
            CP_ASYNC16(bd + row * (BSTRIDE * 2) + c16 * 16,
                       Bsrc + (size_t)(k0 + row) * N_LD + c16 * 8);
        }
        CP_COMMIT();
    };

    const int S = KDIM / 32;
#pragma unroll
    for (int p = 0; p < NSTAGE - 1; p++) issue_stage(p);

    float c[4][8][4];
#pragma unroll
    for (int i = 0; i < 4; i++)
#pragma unroll
        for (int j = 0; j < 8; j++)
#pragma unroll
            for (int k = 0; k < 4; k++) c[i][j][k] = 0.f;

    const int lr = lane & 15;
    const int lh = (lane >> 4) * 8;

#pragma unroll 1
    for (int s = 0; s < S; s++) {
        CP_WAIT2();
        __syncthreads();
        if (s + NSTAGE - 1 < S) issue_stage(s + NSTAGE - 1);
        else CP_COMMIT();

        const int st = s & (NSTAGE - 1);
        const uint32_t sA = sb + SM_OFF_A + st * A_ST_BYTES;
        const uint32_t sB = sb + SM_OFF_B + st * B_ST_BYTES;
#pragma unroll
        for (int kk = 0; kk < 32; kk += 16) {
            uint32_t a[4][4];
#pragma unroll
            for (int mt = 0; mt < 4; mt++)
                ldsm_x4(a[mt], sA + ((warp_m * 64 + mt * 16 + lr) * ASTRIDE + kk + lh) * 2);
            uint32_t bt[4][4];
#pragma unroll
            for (int g = 0; g < 4; g++)
                ldsm_x4_trans(bt[g], sB + ((kk + lr) * BSTRIDE + warp_n * 64 + g * 16 + lh) * 2);
#pragma unroll
            for (int mt = 0; mt < 4; mt++)
#pragma unroll
                for (int nt = 0; nt < 8; nt++)
                    mma16816(c[mt][nt], a[mt],
                             bt[nt >> 1][2 * (nt & 1)], bt[nt >> 1][2 * (nt & 1) + 1]);
        }
        __syncthreads();
    }

    // epilogue: c[mt][nt]: rows warp_m*64+mt*16+(lane>>2)+8h, cols warp_n*64+nt*8+2*(lane&3)
    const int erow = lane >> 2;
    const int ecol = (lane & 3) * 2;
#pragma unroll
    for (int mt = 0; mt < 4; mt++) {
#pragma unroll
        for (int h = 0; h < 2; h++) {
            int ml = warp_m * 64 + mt * 16 + erow + h * 8;
            int packed = sPacked[ml];
            if (packed < 0) continue;
            if (IS_G1) {
                float gate = sGate[ml];
                __half* dst = g_Hh + (size_t)packed * ESIZE + n0 + warp_n * 64 + ecol;
#pragma unroll
                for (int nt = 0; nt < 8; nt++) {
                    float f0 = fmaxf(c[mt][nt][2 * h + 0], 0.f) * gate;
                    float f1 = fmaxf(c[mt][nt][2 * h + 1], 0.f) * gate;
                    *(__half2*)(dst + nt * 8) = __floats2half2_rn(f0, f1);
                }
            } else {
                __half* dst = g_Yph + (size_t)packed * DMODEL + n0 + warp_n * 64 + ecol;
#pragma unroll
                for (int nt = 0; nt < 8; nt++)
                    *(__half2*)(dst + nt * 8) =
                        __floats2half2_rn(c[mt][nt][2 * h + 0], c[mt][nt][2 * h + 1]);
            }
        }
    }
}

// ---------------- reduce: y[t] = sum_slot Yph[t*4+slot] (fp32 accumulate) --------
__global__ __launch_bounds__(256) void reduce_kernel(float* __restrict__ y) {
    int idx = blockIdx.x * blockDim.x + threadIdx.x;   // over NTOK*DMODEL/8
    if (idx >= NTOK * (DMODEL / 8)) return;
    int t  = idx >> 7;          // DMODEL/8 = 128 chunks per row
    int d8 = idx & 127;
    float acc[8];
#pragma unroll
    for (int i = 0; i < 8; i++) acc[i] = 0.f;
#pragma unroll
    for (int sl = 0; sl < TOPK; sl++) {
        uint4 v = *(const uint4*)(g_Yph + ((size_t)(t * TOPK + sl)) * DMODEL + d8 * 8);
        const __half2* h = (const __half2*)&v;
#pragma unroll
        for (int i = 0; i < 4; i++) {
            float2 f = __half22float2(h[i]);
            acc[i * 2 + 0] += f.x;
            acc[i * 2 + 1] += f.y;
        }
    }
    float4* out = (float4*)(y + (size_t)t * DMODEL + d8 * 8);
    out[0] = make_float4(acc[0], acc[1], acc[2], acc[3]);
    out[1] = make_float4(acc[4], acc[5], acc[6], acc[7]);
}

// ---------------- launch ----------------
extern "C" void kernel_launch(void* const* d_in, const int* in_sizes, int n_in,
                              void* d_out, int out_size) {
    const float* x      = (const float*)d_in[0];
    const float* keys   = (const float*)d_in[1];
    const float* values = (const float*)d_in[2];
    const float* esel   = (const float*)d_in[3];
    float*       y      = (float*)d_out;

    cudaFuncSetAttribute(moe_hmma_kernel<DMODEL, ESIZE, true>,
                         cudaFuncAttributeMaxDynamicSharedMemorySize, SM_TOTAL);
    cudaFuncSetAttribute(moe_hmma_kernel<ESIZE, DMODEL, false>,
                         cudaFuncAttributeMaxDynamicSharedMemorySize, SM_TOTAL);

    zero_counts_kernel<<<1, 32>>>();
    route_kernel<<<(NTOK * 32) / 256, 256>>>(x, esel);

    __half* keysH_p;   cudaGetSymbolAddress((void**)&keysH_p, g_keysH);
    __half* valuesH_p; cudaGetSymbolAddress((void**)&valuesH_p, g_valuesH);
    const int wn8 = NEXP * DMODEL * ESIZE / 8;
    convert_h_kernel<<<(wn8 + 255) / 256, 256>>>(keys,   keysH_p,   wn8);
    convert_h_kernel<<<(wn8 + 255) / 256, 256>>>(values, valuesH_p, wn8);

    dim3 g1(1, 64, NEXP);
    moe_hmma_kernel<DMODEL, ESIZE, true><<<g1, 256, SM_TOTAL>>>();

    dim3 g2(4, 64, NEXP);
    moe_hmma_kernel<ESIZE, DMODEL, false><<<g2, 256, SM_TOTAL>>>();

    reduce_kernel<<<(NTOK * (DMODEL / 8) + 255) / 256, 256>>>(y);
}